// round 14
// baseline (speedup 1.0000x reference)
#include <cuda_runtime.h>
#include <mma.h>
#include <cstdint>
#include <cstddef>

using namespace nvcuda;

#define EPSV 1e-5f
#define LDT 20          // smem leading dim for 128x16 tiles (20*4B = 80B, mult of 16B)
#define LDS_STG 20      // epilogue staging tile leading dim

// ---------------- scratch (static device globals; no allocation) ----------------
__device__ float g_H[41472 * 512];
__device__ float g_h1[32768 * 128];
__device__ float g_newxyz[256 * 128 * 3];

// ---------------- threefry2x32 (JAX partitionable path) ----------------
__device__ __forceinline__ void tf_round(uint32_t& v0, uint32_t& v1, int r) {
    v0 += v1;
    v1 = (v1 << r) | (v1 >> (32 - r));
    v1 ^= v0;
}
__device__ __forceinline__ void threefry2x32(uint32_t k0, uint32_t k1,
                                             uint32_t x0, uint32_t x1,
                                             uint32_t& o0, uint32_t& o1) {
    uint32_t ks0 = k0, ks1 = k1, ks2 = k0 ^ k1 ^ 0x1BD11BDAu;
    uint32_t v0 = x0 + ks0, v1 = x1 + ks1;
    tf_round(v0, v1, 13); tf_round(v0, v1, 15); tf_round(v0, v1, 26); tf_round(v0, v1, 6);
    v0 += ks1; v1 += ks2 + 1u;
    tf_round(v0, v1, 17); tf_round(v0, v1, 29); tf_round(v0, v1, 16); tf_round(v0, v1, 24);
    v0 += ks2; v1 += ks0 + 2u;
    tf_round(v0, v1, 13); tf_round(v0, v1, 15); tf_round(v0, v1, 26); tf_round(v0, v1, 6);
    v0 += ks0; v1 += ks1 + 3u;
    tf_round(v0, v1, 17); tf_round(v0, v1, 29); tf_round(v0, v1, 16); tf_round(v0, v1, 24);
    v0 += ks1; v1 += ks2 + 4u;
    tf_round(v0, v1, 13); tf_round(v0, v1, 15); tf_round(v0, v1, 26); tf_round(v0, v1, 6);
    v0 += ks2; v1 += ks0 + 5u;
    o0 = v0; o1 = v1;
}
__device__ __forceinline__ int fps_seed_index(int b) {
    uint32_t ka, kb, ra, rb;
    threefry2x32(0u, 42u, 0u, 1u, ka, kb);
    threefry2x32(ka, kb, 0u, (uint32_t)b, ra, rb);
    return (int)((ra ^ rb) & 4095u);
}

// ---------------- K1: farthest point sampling ----------------
__global__ void __launch_bounds__(256) fps_kernel(const float* __restrict__ pts) {
    __shared__ float rv[8];
    __shared__ int   ri[8];
    __shared__ float sc[3];
    __shared__ int   sFar;

    const int b = blockIdx.x;
    const int t = threadIdx.x;
    const float* P = pts + (size_t)b * 4096 * 3;

    float px[16], py[16], pz[16], dist[16];
#pragma unroll
    for (int k = 0; k < 16; k++) {
        int j = t + k * 256;
        px[k] = P[j * 3 + 0];
        py[k] = P[j * 3 + 1];
        pz[k] = P[j * 3 + 2];
        dist[k] = 1e10f;
    }
    if (t == 0) sFar = fps_seed_index(b);
    __syncthreads();

    {
        int far = sFar;
#pragma unroll
        for (int k = 0; k < 16; k++)
            if (t + k * 256 == far) { sc[0] = px[k]; sc[1] = py[k]; sc[2] = pz[k]; }
    }
    __syncthreads();

    for (int it = 0; it < 128; it++) {
        float cx = sc[0], cy = sc[1], cz = sc[2];
        if (t == 0) {
            float* o = g_newxyz + ((size_t)b * 128 + it) * 3;
            o[0] = cx; o[1] = cy; o[2] = cz;
        }
        float best = -1.0f;
        int bi = 0x7fffffff;
#pragma unroll
        for (int k = 0; k < 16; k++) {
            int j = t + k * 256;
            float dx = px[k] - cx, dy = py[k] - cy, dz = pz[k] - cz;
            float d = dx * dx + dy * dy + dz * dz;
            float nd = fminf(dist[k], d);
            dist[k] = nd;
            if (nd > best) { best = nd; bi = j; }
        }
#pragma unroll
        for (int off = 16; off; off >>= 1) {
            float ov = __shfl_down_sync(0xffffffffu, best, off);
            int   oi = __shfl_down_sync(0xffffffffu, bi, off);
            if (ov > best || (ov == best && oi < bi)) { best = ov; bi = oi; }
        }
        if ((t & 31) == 0) { rv[t >> 5] = best; ri[t >> 5] = bi; }
        __syncthreads();
        if (t < 32) {
            float v = (t < 8) ? rv[t] : -1e30f;
            int   ix = (t < 8) ? ri[t] : 0x7fffffff;
#pragma unroll
            for (int off = 4; off; off >>= 1) {
                float ov = __shfl_down_sync(0xffffffffu, v, off);
                int   oi = __shfl_down_sync(0xffffffffu, ix, off);
                if (ov > v || (ov == v && oi < ix)) { v = ov; ix = oi; }
            }
            if (t == 0) sFar = ix;
        }
        __syncthreads();
        {
            int far = sFar;
#pragma unroll
            for (int k = 0; k < 16; k++)
                if (t + k * 256 == far) { sc[0] = px[k]; sc[1] = py[k]; sc[2] = pz[k]; }
        }
        __syncthreads();
    }
}

// tf32-round a float4 (stage-time conversion; fragments then load pre-rounded data)
__device__ __forceinline__ float4 cvt4_tf32(float4 v) {
    v.x = wmma::__float_to_tf32(v.x);
    v.y = wmma::__float_to_tf32(v.y);
    v.z = wmma::__float_to_tf32(v.z);
    v.w = wmma::__float_to_tf32(v.w);
    return v;
}

// ---------------- K2: fused stage-1 wmma tf32 GEMM + BN + ReLU (double-buffered) -------
// grid (324, 4): blocks 0-97 rgb, 98-195 depth, 196-259 mmwave, 260-323 lidar
__global__ void __launch_bounds__(256, 2) wmma_stage1_kernel(
    const float* __restrict__ rgb, const float* __restrict__ depth,
    const float* __restrict__ mmw, const float* __restrict__ lid,
    const float* __restrict__ conv_w, const float* __restrict__ cb4,
    const float* __restrict__ gg4, const float* __restrict__ bb4,
    const float* __restrict__ bm4, const float* __restrict__ bv4)
{
    __shared__ float As[2][128 * LDT];
    __shared__ float Bs[2][128 * LDT];
    __shared__ float s_alpha[128], s_beta[128];

    const int blk = blockIdx.x;
    int mod, rb, region;
    if (blk < 98)       { mod = 0; rb = blk;       region = 0; }
    else if (blk < 196) { mod = 1; rb = blk - 98;  region = 12544; }
    else if (blk < 260) { mod = 2; rb = blk - 196; region = 25088; }
    else                { mod = 3; rb = blk - 260; region = 33280; }
    const float* X  = (mod == 0) ? rgb : (mod == 1) ? depth : (mod == 2) ? mmw : lid;
    const float* W  = conv_w + (size_t)mod * 262144;

    const int row0 = rb * 128;
    const int col0 = blockIdx.y * 128;
    const int t = threadIdx.x;

    if (t < 128) {
        int o = col0 + t;
        float al = gg4[mod * 512 + o] * rsqrtf(bv4[mod * 512 + o] + EPSV);
        s_alpha[t] = al;
        s_beta[t]  = (cb4[mod * 512 + o] - bm4[mod * 512 + o]) * al + bb4[mod * 512 + o];
    }

    const int wid = t >> 5, lane = t & 31;
    const int wm = wid & 3, wn = wid >> 2;

    wmma::fragment<wmma::accumulator, 16, 16, 8, float> c[2][4];
#pragma unroll
    for (int i = 0; i < 2; i++)
#pragma unroll
        for (int j = 0; j < 4; j++) wmma::fill_fragment(c[i][j], 0.0f);

    // staging thread mapping: thread handles rows r0 and r0+64, float4 q0 of the 16-wide slab
    const int r0 = t >> 2;      // 0..63
    const int q0 = t & 3;
    const float* Ap0 = X + (size_t)(row0 + r0) * 512 + q0 * 4;
    const float* Ap1 = Ap0 + (size_t)64 * 512;
    const float* Bp0 = W + (size_t)(col0 + r0) * 512 + q0 * 4;
    const float* Bp1 = Bp0 + (size_t)64 * 512;
    float* sa0 = &As[0][r0 * LDT + q0 * 4];
    float* sa1 = sa0 + 64 * LDT;
    float* sb0 = &Bs[0][r0 * LDT + q0 * 4];
    float* sb1 = sb0 + 64 * LDT;
    const int bufStride = 128 * LDT;

    // prologue: stage tile 0
    *(float4*)sa0 = cvt4_tf32(*(const float4*)Ap0);
    *(float4*)sa1 = cvt4_tf32(*(const float4*)Ap1);
    *(float4*)sb0 = cvt4_tf32(*(const float4*)Bp0);
    *(float4*)sb1 = cvt4_tf32(*(const float4*)Bp1);
    __syncthreads();

    for (int kt = 0; kt < 32; kt++) {
        const int buf = kt & 1;
        const bool more = (kt + 1) < 32;
        float4 a0, a1, b0, b1;
        if (more) {
            const int ko = (kt + 1) * 16;
            a0 = *(const float4*)(Ap0 + ko);
            a1 = *(const float4*)(Ap1 + ko);
            b0 = *(const float4*)(Bp0 + ko);
            b1 = *(const float4*)(Bp1 + ko);
        }
#pragma unroll
        for (int ks = 0; ks < 2; ks++) {
            const int k0 = ks * 8;
            wmma::fragment<wmma::matrix_a, 16, 16, 8, wmma::precision::tf32, wmma::row_major> a[2];
            wmma::fragment<wmma::matrix_b, 16, 16, 8, wmma::precision::tf32, wmma::col_major> b[4];
#pragma unroll
            for (int i = 0; i < 2; i++)
                wmma::load_matrix_sync(a[i], &As[buf][(wm * 32 + i * 16) * LDT + k0], LDT);
#pragma unroll
            for (int j = 0; j < 4; j++)
                wmma::load_matrix_sync(b[j], &Bs[buf][(wn * 64 + j * 16) * LDT + k0], LDT);
#pragma unroll
            for (int i = 0; i < 2; i++)
#pragma unroll
                for (int j = 0; j < 4; j++)
                    wmma::mma_sync(c[i][j], a[i], b[j], c[i][j]);
        }
        if (more) {
            const int off = (buf ^ 1) * bufStride;
            *(float4*)(sa0 + off) = cvt4_tf32(a0);
            *(float4*)(sa1 + off) = cvt4_tf32(a1);
            *(float4*)(sb0 + off) = cvt4_tf32(b0);
            *(float4*)(sb1 + off) = cvt4_tf32(b1);
        }
        __syncthreads();
    }

    // epilogue: BN + ReLU through per-warp staging tile (reuse As[0])
    float* stg = &As[0][0] + wid * (16 * LDS_STG);
    const int r = lane >> 1, cs = (lane & 1) * 8;
#pragma unroll
    for (int i = 0; i < 2; i++)
#pragma unroll
        for (int j = 0; j < 4; j++) {
            wmma::store_matrix_sync(stg, c[i][j], LDS_STG, wmma::mem_row_major);
            __syncwarp();
            const int gc = wn * 64 + j * 16 + cs;
            float ov[8];
#pragma unroll
            for (int q = 0; q < 8; q++) {
                float v = stg[r * LDS_STG + cs + q];
                ov[q] = fmaxf(fmaf(v, s_alpha[gc + q], s_beta[gc + q]), 0.0f);
            }
            float* hp = g_H + (size_t)(region + row0 + wm * 32 + i * 16 + r) * 512 + col0 + gc;
            *(float4*)hp       = make_float4(ov[0], ov[1], ov[2], ov[3]);
            *(float4*)(hp + 4) = make_float4(ov[4], ov[5], ov[6], ov[7]);
            __syncwarp();
        }
}

// ---------------- K3: token linear (L -> 32) + ReLU, writes proj into d_out ----------------
__global__ void __launch_bounds__(256) stage2_kernel(
    const float* __restrict__ lwimg, const float* __restrict__ lbimg,
    const float* __restrict__ lwpc,  const float* __restrict__ lbpc,
    float* __restrict__ out)
{
    const int b = blockIdx.x, m = blockIdx.y, t = threadIdx.x;
    const int L = (m < 2) ? 49 : 32;
    const int start = (m < 2) ? m * 12544 : 25088 + (m - 2) * 8192;
    const float* lw = (m == 0) ? lwimg
                    : (m == 1) ? lwimg + 32 * 49
                    : (m == 2) ? lwpc
                               : lwpc + 32 * 32;
    const float* lb = (m < 2) ? lbimg + m * 32 : lbpc + (m - 2) * 32;

    __shared__ float slw[32 * 49];
    for (int i = t; i < 32 * L; i += 256) slw[i] = lw[i];
    __syncthreads();

    const int o0 = (t & 63) * 8;
    const int s0 = (t >> 6) * 8;
    float acc[8][8];
#pragma unroll
    for (int i = 0; i < 8; i++)
#pragma unroll
        for (int j = 0; j < 8; j++) acc[i][j] = 0.0f;

    const float* hp = g_H + (size_t)(start + b * L) * 512 + o0;
    for (int l = 0; l < L; l++) {
        float4 h0 = *(const float4*)hp;
        float4 h1 = *(const float4*)(hp + 4);
        hp += 512;
        float hv[8] = {h0.x, h0.y, h0.z, h0.w, h1.x, h1.y, h1.z, h1.w};
#pragma unroll
        for (int i = 0; i < 8; i++) {
            float w = slw[(s0 + i) * L + l];
#pragma unroll
            for (int j = 0; j < 8; j++) acc[i][j] = fmaf(w, hv[j], acc[i][j]);
        }
    }
#pragma unroll
    for (int i = 0; i < 8; i++) {
        int s = s0 + i;
        float bias = lb[s];
        float ov[8];
#pragma unroll
        for (int j = 0; j < 8; j++) ov[j] = fmaxf(acc[i][j] + bias, 0.0f);
        float* op = out + ((size_t)b * 128 + m * 32 + s) * 512 + o0;
        *(float4*)op       = make_float4(ov[0], ov[1], ov[2], ov[3]);
        *(float4*)(op + 4) = make_float4(ov[4], ov[5], ov[6], ov[7]);
    }
}

// ---------------- K4a: posenc layer 1 (3 -> 128) + BN + ReLU ----------------
__global__ void __launch_bounds__(256) h1_kernel(
    const float* __restrict__ w1, const float* __restrict__ b1,
    const float* __restrict__ g1, const float* __restrict__ bb1,
    const float* __restrict__ m1, const float* __restrict__ v1)
{
    int idx = blockIdx.x * 256 + threadIdx.x;
    int row = idx >> 7;
    int c = idx & 127;
    const float* xyz = g_newxyz + (size_t)row * 3;
    float x = xyz[0], y = xyz[1], z = xyz[2];
    float v = w1[c * 3 + 0] * x + w1[c * 3 + 1] * y + w1[c * 3 + 2] * z + b1[c];
    float al = g1[c] * rsqrtf(v1[c] + EPSV);
    v = (v - m1[c]) * al + bb1[c];
    g_h1[(size_t)row * 128 + c] = fmaxf(v, 0.0f);
}

// ---------------- K4b: posenc layer-2 wmma tf32 GEMM + BN + ReLU, += out ----------------
__global__ void __launch_bounds__(256, 2) wmma_posenc_kernel(
    const float* __restrict__ W,     // pe_w2 [512, 128], K contiguous
    const float* __restrict__ cb,
    const float* __restrict__ gg,
    const float* __restrict__ bbeta,
    const float* __restrict__ bmean,
    const float* __restrict__ bvar,
    float* __restrict__ out)
{
    __shared__ float As[2][128 * LDT];
    __shared__ float Bs[2][128 * LDT];
    __shared__ float s_alpha[128], s_beta[128];

    const int row0 = blockIdx.x * 128;
    const int col0 = blockIdx.y * 128;
    const int t = threadIdx.x;

    if (t < 128) {
        int o = col0 + t;
        float al = gg[o] * rsqrtf(bvar[o] + EPSV);
        s_alpha[t] = al;
        s_beta[t]  = (cb[o] - bmean[o]) * al + bbeta[o];
    }

    const int wid = t >> 5, lane = t & 31;
    const int wm = wid & 3, wn = wid >> 2;

    wmma::fragment<wmma::accumulator, 16, 16, 8, float> c[2][4];
#pragma unroll
    for (int i = 0; i < 2; i++)
#pragma unroll
        for (int j = 0; j < 4; j++) wmma::fill_fragment(c[i][j], 0.0f);

    const int r0 = t >> 2;
    const int q0 = t & 3;
    const float* Ap0 = g_h1 + (size_t)(row0 + r0) * 128 + q0 * 4;
    const float* Ap1 = Ap0 + (size_t)64 * 128;
    const float* Bp0 = W + (size_t)(col0 + r0) * 128 + q0 * 4;
    const float* Bp1 = Bp0 + (size_t)64 * 128;
    float* sa0 = &As[0][r0 * LDT + q0 * 4];
    float* sa1 = sa0 + 64 * LDT;
    float* sb0 = &Bs[0][r0 * LDT + q0 * 4];
    float* sb1 = sb0 + 64 * LDT;
    const int bufStride = 128 * LDT;

    *(float4*)sa0 = cvt4_tf32(*(const float4*)Ap0);
    *(float4*)sa1 = cvt4_tf32(*(const float4*)Ap1);
    *(float4*)sb0 = cvt4_tf32(*(const float4*)Bp0);
    *(float4*)sb1 = cvt4_tf32(*(const float4*)Bp1);
    __syncthreads();

    for (int kt = 0; kt < 8; kt++) {
        const int buf = kt & 1;
        const bool more = (kt + 1) < 8;
        float4 a0, a1, b0, b1;
        if (more) {
            const int ko = (kt + 1) * 16;
            a0 = *(const float4*)(Ap0 + ko);
            a1 = *(const float4*)(Ap1 + ko);
            b0 = *(const float4*)(Bp0 + ko);
            b1 = *(const float4*)(Bp1 + ko);
        }
#pragma unroll
        for (int ks = 0; ks < 2; ks++) {
            const int k0 = ks * 8;
            wmma::fragment<wmma::matrix_a, 16, 16, 8, wmma::precision::tf32, wmma::row_major> a[2];
            wmma::fragment<wmma::matrix_b, 16, 16, 8, wmma::precision::tf32, wmma::col_major> b[4];
#pragma unroll
            for (int i = 0; i < 2; i++)
                wmma::load_matrix_sync(a[i], &As[buf][(wm * 32 + i * 16) * LDT + k0], LDT);
#pragma unroll
            for (int j = 0; j < 4; j++)
                wmma::load_matrix_sync(b[j], &Bs[buf][(wn * 64 + j * 16) * LDT + k0], LDT);
#pragma unroll
            for (int i = 0; i < 2; i++)
#pragma unroll
                for (int j = 0; j < 4; j++)
                    wmma::mma_sync(c[i][j], a[i], b[j], c[i][j]);
        }
        if (more) {
            const int off = (buf ^ 1) * bufStride;
            *(float4*)(sa0 + off) = cvt4_tf32(a0);
            *(float4*)(sa1 + off) = cvt4_tf32(a1);
            *(float4*)(sb0 + off) = cvt4_tf32(b0);
            *(float4*)(sb1 + off) = cvt4_tf32(b1);
        }
        __syncthreads();
    }

    float* stg = &As[0][0] + wid * (16 * LDS_STG);
    const int r = lane >> 1, cs = (lane & 1) * 8;
#pragma unroll
    for (int i = 0; i < 2; i++)
#pragma unroll
        for (int j = 0; j < 4; j++) {
            wmma::store_matrix_sync(stg, c[i][j], LDS_STG, wmma::mem_row_major);
            __syncwarp();
            const int gc = wn * 64 + j * 16 + cs;
            float* op = out + (size_t)(row0 + wm * 32 + i * 16 + r) * 512 + col0 + gc;
            float4 c0 = *(float4*)op;
            float4 c1 = *(float4*)(op + 4);
            float v0 = stg[r * LDS_STG + cs + 0];
            float v1 = stg[r * LDS_STG + cs + 1];
            float v2 = stg[r * LDS_STG + cs + 2];
            float v3 = stg[r * LDS_STG + cs + 3];
            float v4 = stg[r * LDS_STG + cs + 4];
            float v5 = stg[r * LDS_STG + cs + 5];
            float v6 = stg[r * LDS_STG + cs + 6];
            float v7 = stg[r * LDS_STG + cs + 7];
            c0.x += fmaxf(fmaf(v0, s_alpha[gc + 0], s_beta[gc + 0]), 0.0f);
            c0.y += fmaxf(fmaf(v1, s_alpha[gc + 1], s_beta[gc + 1]), 0.0f);
            c0.z += fmaxf(fmaf(v2, s_alpha[gc + 2], s_beta[gc + 2]), 0.0f);
            c0.w += fmaxf(fmaf(v3, s_alpha[gc + 3], s_beta[gc + 3]), 0.0f);
            c1.x += fmaxf(fmaf(v4, s_alpha[gc + 4], s_beta[gc + 4]), 0.0f);
            c1.y += fmaxf(fmaf(v5, s_alpha[gc + 5], s_beta[gc + 5]), 0.0f);
            c1.z += fmaxf(fmaf(v6, s_alpha[gc + 6], s_beta[gc + 6]), 0.0f);
            c1.w += fmaxf(fmaf(v7, s_alpha[gc + 7], s_beta[gc + 7]), 0.0f);
            *(float4*)op       = c0;
            *(float4*)(op + 4) = c1;
            __syncwarp();
        }
}

// ---------------- launch ----------------
extern "C" void kernel_launch(void* const* d_in, const int* in_sizes, int n_in,
                              void* d_out, int out_size) {
    const float* rgb     = (const float*)d_in[0];
    const float* depth   = (const float*)d_in[1];
    const float* mmwave  = (const float*)d_in[2];
    const float* lidar   = (const float*)d_in[3];
    const float* pts     = (const float*)d_in[4];
    const float* conv_w  = (const float*)d_in[5];
    const float* conv_b  = (const float*)d_in[6];
    const float* bn_g    = (const float*)d_in[7];
    const float* bn_b    = (const float*)d_in[8];
    const float* bn_m    = (const float*)d_in[9];
    const float* bn_v    = (const float*)d_in[10];
    const float* lwimg   = (const float*)d_in[11];
    const float* lbimg   = (const float*)d_in[12];
    const float* lwpc    = (const float*)d_in[13];
    const float* lbpc    = (const float*)d_in[14];
    const float* pw1     = (const float*)d_in[15];
    const float* pb1     = (const float*)d_in[16];
    const float* pg1     = (const float*)d_in[17];
    const float* pbb1    = (const float*)d_in[18];
    const float* pm1     = (const float*)d_in[19];
    const float* pv1     = (const float*)d_in[20];
    const float* pw2     = (const float*)d_in[21];
    const float* pb2     = (const float*)d_in[22];
    const float* pg2     = (const float*)d_in[23];
    const float* pbb2    = (const float*)d_in[24];
    const float* pm2     = (const float*)d_in[25];
    const float* pv2     = (const float*)d_in[26];
    float* out = (float*)d_out;

    // FPS (independent of GEMMs)
    fps_kernel<<<256, 256>>>(pts);

    // stage-1: all 4 modalities in one fused tf32 wmma launch (double-buffered)
    wmma_stage1_kernel<<<dim3(324, 4), 256>>>(rgb, depth, mmwave, lidar,
                                              conv_w, conv_b, bn_g, bn_b, bn_m, bn_v);

    // stage-2: proj written to d_out
    stage2_kernel<<<dim3(256, 4), 256>>>(lwimg, lbimg, lwpc, lbpc, out);

    // posenc layer 1 (elementwise) then layer-2 tf32 GEMM accumulated into d_out
    h1_kernel<<<16384, 256>>>(pw1, pb1, pg1, pbb1, pm1, pv1);
    wmma_posenc_kernel<<<dim3(256, 4), 256>>>(pw2, pb2, pg2, pbb2, pm2, pv2, out);
}

// round 15
// speedup vs baseline: 1.3145x; 1.3145x over previous
#include <cuda_runtime.h>
#include <mma.h>
#include <cstdint>
#include <cstddef>

using namespace nvcuda;

#define EPSV 1e-5f
#define LDA 36          // smem leading dim for 128x32 tiles (known-good R10 layout)
#define LDS_STG 20      // epilogue staging tile leading dim

// ---------------- scratch (static device globals; no allocation) ----------------
__device__ float g_H[41472 * 512];
__device__ float g_newxyz[256 * 128 * 3];

// ---------------- threefry2x32 (JAX partitionable path) ----------------
__device__ __forceinline__ void tf_round(uint32_t& v0, uint32_t& v1, int r) {
    v0 += v1;
    v1 = (v1 << r) | (v1 >> (32 - r));
    v1 ^= v0;
}
__device__ __forceinline__ void threefry2x32(uint32_t k0, uint32_t k1,
                                             uint32_t x0, uint32_t x1,
                                             uint32_t& o0, uint32_t& o1) {
    uint32_t ks0 = k0, ks1 = k1, ks2 = k0 ^ k1 ^ 0x1BD11BDAu;
    uint32_t v0 = x0 + ks0, v1 = x1 + ks1;
    tf_round(v0, v1, 13); tf_round(v0, v1, 15); tf_round(v0, v1, 26); tf_round(v0, v1, 6);
    v0 += ks1; v1 += ks2 + 1u;
    tf_round(v0, v1, 17); tf_round(v0, v1, 29); tf_round(v0, v1, 16); tf_round(v0, v1, 24);
    v0 += ks2; v1 += ks0 + 2u;
    tf_round(v0, v1, 13); tf_round(v0, v1, 15); tf_round(v0, v1, 26); tf_round(v0, v1, 6);
    v0 += ks0; v1 += ks1 + 3u;
    tf_round(v0, v1, 17); tf_round(v0, v1, 29); tf_round(v0, v1, 16); tf_round(v0, v1, 24);
    v0 += ks1; v1 += ks2 + 4u;
    tf_round(v0, v1, 13); tf_round(v0, v1, 15); tf_round(v0, v1, 26); tf_round(v0, v1, 6);
    v0 += ks2; v1 += ks0 + 5u;
    o0 = v0; o1 = v1;
}
__device__ __forceinline__ int fps_seed_index(int b) {
    uint32_t ka, kb, ra, rb;
    threefry2x32(0u, 42u, 0u, 1u, ka, kb);
    threefry2x32(ka, kb, 0u, (uint32_t)b, ra, rb);
    return (int)((ra ^ rb) & 4095u);
}

// ---------------- K1: farthest point sampling ----------------
__global__ void __launch_bounds__(256) fps_kernel(const float* __restrict__ pts) {
    __shared__ float rv[8];
    __shared__ int   ri[8];
    __shared__ float sc[3];
    __shared__ int   sFar;

    const int b = blockIdx.x;
    const int t = threadIdx.x;
    const float* P = pts + (size_t)b * 4096 * 3;

    float px[16], py[16], pz[16], dist[16];
#pragma unroll
    for (int k = 0; k < 16; k++) {
        int j = t + k * 256;
        px[k] = P[j * 3 + 0];
        py[k] = P[j * 3 + 1];
        pz[k] = P[j * 3 + 2];
        dist[k] = 1e10f;
    }
    if (t == 0) sFar = fps_seed_index(b);
    __syncthreads();

    {
        int far = sFar;
#pragma unroll
        for (int k = 0; k < 16; k++)
            if (t + k * 256 == far) { sc[0] = px[k]; sc[1] = py[k]; sc[2] = pz[k]; }
    }
    __syncthreads();

    for (int it = 0; it < 128; it++) {
        float cx = sc[0], cy = sc[1], cz = sc[2];
        if (t == 0) {
            float* o = g_newxyz + ((size_t)b * 128 + it) * 3;
            o[0] = cx; o[1] = cy; o[2] = cz;
        }
        float best = -1.0f;
        int bi = 0x7fffffff;
#pragma unroll
        for (int k = 0; k < 16; k++) {
            int j = t + k * 256;
            float dx = px[k] - cx, dy = py[k] - cy, dz = pz[k] - cz;
            float d = dx * dx + dy * dy + dz * dz;
            float nd = fminf(dist[k], d);
            dist[k] = nd;
            if (nd > best) { best = nd; bi = j; }
        }
#pragma unroll
        for (int off = 16; off; off >>= 1) {
            float ov = __shfl_down_sync(0xffffffffu, best, off);
            int   oi = __shfl_down_sync(0xffffffffu, bi, off);
            if (ov > best || (ov == best && oi < bi)) { best = ov; bi = oi; }
        }
        if ((t & 31) == 0) { rv[t >> 5] = best; ri[t >> 5] = bi; }
        __syncthreads();
        if (t < 32) {
            float v = (t < 8) ? rv[t] : -1e30f;
            int   ix = (t < 8) ? ri[t] : 0x7fffffff;
#pragma unroll
            for (int off = 4; off; off >>= 1) {
                float ov = __shfl_down_sync(0xffffffffu, v, off);
                int   oi = __shfl_down_sync(0xffffffffu, ix, off);
                if (ov > v || (ov == v && oi < ix)) { v = ov; ix = oi; }
            }
            if (t == 0) sFar = ix;
        }
        __syncthreads();
        {
            int far = sFar;
#pragma unroll
            for (int k = 0; k < 16; k++)
                if (t + k * 256 == far) { sc[0] = px[k]; sc[1] = py[k]; sc[2] = pz[k]; }
        }
        __syncthreads();
    }
}

// tf32-round a float4 at staging time (numerically identical to fragment-time cvt)
__device__ __forceinline__ float4 cvt4_tf32(float4 v) {
    v.x = wmma::__float_to_tf32(v.x);
    v.y = wmma::__float_to_tf32(v.y);
    v.z = wmma::__float_to_tf32(v.z);
    v.w = wmma::__float_to_tf32(v.w);
    return v;
}

// smem tile loader: 128 rows x 32 floats, tf32-rounded at store
__device__ __forceinline__ void load_tile_cvt(const float* __restrict__ gptr, int ldg,
                                              float* sptr, int t) {
#pragma unroll
    for (int i = 0; i < 4; i++) {
        int idx = t + i * 256;          // float4 index 0..1023
        int row = idx >> 3, q = idx & 7;
        float4 v = *(const float4*)(gptr + (size_t)row * ldg + q * 4);
        *(float4*)(sptr + row * LDA + q * 4) = cvt4_tf32(v);
    }
}

// ---------------- K2: fused stage-1 wmma tf32 GEMM + BN + ReLU ----------------
// grid (324, 4): blocks 0-97 rgb, 98-195 depth, 196-259 mmwave, 260-323 lidar
__global__ void __launch_bounds__(256) wmma_stage1_kernel(
    const float* __restrict__ rgb, const float* __restrict__ depth,
    const float* __restrict__ mmw, const float* __restrict__ lid,
    const float* __restrict__ conv_w, const float* __restrict__ cb4,
    const float* __restrict__ gg4, const float* __restrict__ bb4,
    const float* __restrict__ bm4, const float* __restrict__ bv4)
{
    __shared__ float As[128 * LDA];
    __shared__ float Bs[128 * LDA];
    __shared__ float s_alpha[128], s_beta[128];

    const int blk = blockIdx.x;
    int mod, rb, region;
    if (blk < 98)       { mod = 0; rb = blk;       region = 0; }
    else if (blk < 196) { mod = 1; rb = blk - 98;  region = 12544; }
    else if (blk < 260) { mod = 2; rb = blk - 196; region = 25088; }
    else                { mod = 3; rb = blk - 260; region = 33280; }
    const float* X  = (mod == 0) ? rgb : (mod == 1) ? depth : (mod == 2) ? mmw : lid;
    const float* W  = conv_w + (size_t)mod * 262144;

    const int row0 = rb * 128;
    const int col0 = blockIdx.y * 128;
    const int t = threadIdx.x;

    if (t < 128) {
        int o = col0 + t;
        float al = gg4[mod * 512 + o] * rsqrtf(bv4[mod * 512 + o] + EPSV);
        s_alpha[t] = al;
        s_beta[t]  = (cb4[mod * 512 + o] - bm4[mod * 512 + o]) * al + bb4[mod * 512 + o];
    }

    const int wid = t >> 5, lane = t & 31;
    const int wm = wid & 3, wn = wid >> 2;

    wmma::fragment<wmma::accumulator, 16, 16, 8, float> c[2][4];
#pragma unroll
    for (int i = 0; i < 2; i++)
#pragma unroll
        for (int j = 0; j < 4; j++) wmma::fill_fragment(c[i][j], 0.0f);

    const float* Ab = X + (size_t)row0 * 512;
    const float* Bb = W + (size_t)col0 * 512;

    for (int kt = 0; kt < 16; kt++) {
        load_tile_cvt(Ab + kt * 32, 512, As, t);
        load_tile_cvt(Bb + kt * 32, 512, Bs, t);
        __syncthreads();
#pragma unroll
        for (int ks = 0; ks < 4; ks++) {
            const int k0 = ks * 8;
            wmma::fragment<wmma::matrix_a, 16, 16, 8, wmma::precision::tf32, wmma::row_major> a[2];
            wmma::fragment<wmma::matrix_b, 16, 16, 8, wmma::precision::tf32, wmma::col_major> b[4];
#pragma unroll
            for (int i = 0; i < 2; i++)
                wmma::load_matrix_sync(a[i], As + (wm * 32 + i * 16) * LDA + k0, LDA);
#pragma unroll
            for (int j = 0; j < 4; j++)
                wmma::load_matrix_sync(b[j], Bs + (wn * 64 + j * 16) * LDA + k0, LDA);
#pragma unroll
            for (int i = 0; i < 2; i++)
#pragma unroll
                for (int j = 0; j < 4; j++)
                    wmma::mma_sync(c[i][j], a[i], b[j], c[i][j]);
        }
        __syncthreads();
    }

    // epilogue: BN + ReLU through tiny per-warp staging tile
    float* stg = As + wid * (16 * LDS_STG);
    const int r = lane >> 1, cs = (lane & 1) * 8;
#pragma unroll
    for (int i = 0; i < 2; i++)
#pragma unroll
        for (int j = 0; j < 4; j++) {
            wmma::store_matrix_sync(stg, c[i][j], LDS_STG, wmma::mem_row_major);
            __syncwarp();
            const int gc = wn * 64 + j * 16 + cs;
            float ov[8];
#pragma unroll
            for (int q = 0; q < 8; q++) {
                float v = stg[r * LDS_STG + cs + q];
                ov[q] = fmaxf(fmaf(v, s_alpha[gc + q], s_beta[gc + q]), 0.0f);
            }
            float* hp = g_H + (size_t)(region + row0 + wm * 32 + i * 16 + r) * 512 + col0 + gc;
            *(float4*)hp       = make_float4(ov[0], ov[1], ov[2], ov[3]);
            *(float4*)(hp + 4) = make_float4(ov[4], ov[5], ov[6], ov[7]);
            __syncwarp();
        }
}

// ---------------- K3: token linear (L -> 32) + ReLU, writes proj into d_out ----------------
__global__ void __launch_bounds__(256) stage2_kernel(
    const float* __restrict__ lwimg, const float* __restrict__ lbimg,
    const float* __restrict__ lwpc,  const float* __restrict__ lbpc,
    float* __restrict__ out)
{
    const int b = blockIdx.x, m = blockIdx.y, t = threadIdx.x;
    const int L = (m < 2) ? 49 : 32;
    const int start = (m < 2) ? m * 12544 : 25088 + (m - 2) * 8192;
    const float* lw = (m == 0) ? lwimg
                    : (m == 1) ? lwimg + 32 * 49
                    : (m == 2) ? lwpc
                               : lwpc + 32 * 32;
    const float* lb = (m < 2) ? lbimg + m * 32 : lbpc + (m - 2) * 32;

    __shared__ float slw[32 * 49];
    for (int i = t; i < 32 * L; i += 256) slw[i] = lw[i];
    __syncthreads();

    const int o0 = (t & 63) * 8;
    const int s0 = (t >> 6) * 8;
    float acc[8][8];
#pragma unroll
    for (int i = 0; i < 8; i++)
#pragma unroll
        for (int j = 0; j < 8; j++) acc[i][j] = 0.0f;

    const float* hp = g_H + (size_t)(start + b * L) * 512 + o0;
    for (int l = 0; l < L; l++) {
        float4 h0 = *(const float4*)hp;
        float4 h1 = *(const float4*)(hp + 4);
        hp += 512;
        float hv[8] = {h0.x, h0.y, h0.z, h0.w, h1.x, h1.y, h1.z, h1.w};
#pragma unroll
        for (int i = 0; i < 8; i++) {
            float w = slw[(s0 + i) * L + l];
#pragma unroll
            for (int j = 0; j < 8; j++) acc[i][j] = fmaf(w, hv[j], acc[i][j]);
        }
    }
#pragma unroll
    for (int i = 0; i < 8; i++) {
        int s = s0 + i;
        float bias = lb[s];
        float ov[8];
#pragma unroll
        for (int j = 0; j < 8; j++) ov[j] = fmaxf(acc[i][j] + bias, 0.0f);
        float* op = out + ((size_t)b * 128 + m * 32 + s) * 512 + o0;
        *(float4*)op       = make_float4(ov[0], ov[1], ov[2], ov[3]);
        *(float4*)(op + 4) = make_float4(ov[4], ov[5], ov[6], ov[7]);
    }
}

// ---------------- K4: posenc fused (layer1 computed in A-staging) + layer-2 GEMM -------
// grid (256, 4): row0 = bx*128 over 32768 sampled points, col0 = by*128 over OUT
__global__ void __launch_bounds__(256) wmma_posenc_kernel(
    const float* __restrict__ w1, const float* __restrict__ b1,
    const float* __restrict__ g1, const float* __restrict__ bb1,
    const float* __restrict__ m1, const float* __restrict__ v1,
    const float* __restrict__ W,     // pe_w2 [512, 128], K contiguous
    const float* __restrict__ cb,
    const float* __restrict__ gg,
    const float* __restrict__ bbeta,
    const float* __restrict__ bmean,
    const float* __restrict__ bvar,
    float* __restrict__ out)
{
    __shared__ float As[128 * LDA];
    __shared__ float Bs[128 * LDA];
    __shared__ float s_alpha[128], s_beta[128];
    __shared__ float s_w1[128 * 3], s_al1[128], s_be1[128];

    const int row0 = blockIdx.x * 128;
    const int col0 = blockIdx.y * 128;
    const int t = threadIdx.x;

    if (t < 128) {
        int o = col0 + t;
        float al = gg[o] * rsqrtf(bvar[o] + EPSV);
        s_alpha[t] = al;
        s_beta[t]  = (cb[o] - bmean[o]) * al + bbeta[o];
        // layer-1 BN constants (channel t)
        float al1 = g1[t] * rsqrtf(v1[t] + EPSV);
        s_al1[t] = al1;
        s_be1[t] = (b1[t] - m1[t]) * al1 + bb1[t];
        s_w1[t * 3 + 0] = w1[t * 3 + 0];
        s_w1[t * 3 + 1] = w1[t * 3 + 1];
        s_w1[t * 3 + 2] = w1[t * 3 + 2];
    }
    __syncthreads();

    const int wid = t >> 5, lane = t & 31;
    const int wm = wid & 3, wn = wid >> 2;

    wmma::fragment<wmma::accumulator, 16, 16, 8, float> c[2][4];
#pragma unroll
    for (int i = 0; i < 2; i++)
#pragma unroll
        for (int j = 0; j < 4; j++) wmma::fill_fragment(c[i][j], 0.0f);

    const float* Bb = W + (size_t)col0 * 128;

    for (int kt = 0; kt < 4; kt++) {
        // A-tile: compute h1 = relu(bn(w1 . xyz)) for rows [row0..row0+128), ch kt*32..+32
#pragma unroll
        for (int i = 0; i < 4; i++) {
            int idx = t + i * 256;          // float4 index 0..1023
            int row = idx >> 3, q = idx & 7;
            const float* xyz = g_newxyz + (size_t)(row0 + row) * 3;
            float x = xyz[0], y = xyz[1], z = xyz[2];
            float ov[4];
#pragma unroll
            for (int e = 0; e < 4; e++) {
                int cch = kt * 32 + q * 4 + e;
                float v = s_w1[cch * 3 + 0] * x + s_w1[cch * 3 + 1] * y + s_w1[cch * 3 + 2] * z;
                v = fmaf(v, s_al1[cch], s_be1[cch]);
                ov[e] = wmma::__float_to_tf32(fmaxf(v, 0.0f));
            }
            *(float4*)(As + row * LDA + q * 4) = make_float4(ov[0], ov[1], ov[2], ov[3]);
        }
        load_tile_cvt(Bb + kt * 32, 128, Bs, t);
        __syncthreads();
#pragma unroll
        for (int ks = 0; ks < 4; ks++) {
            const int k0 = ks * 8;
            wmma::fragment<wmma::matrix_a, 16, 16, 8, wmma::precision::tf32, wmma::row_major> a[2];
            wmma::fragment<wmma::matrix_b, 16, 16, 8, wmma::precision::tf32, wmma::col_major> b[4];
#pragma unroll
            for (int i = 0; i < 2; i++)
                wmma::load_matrix_sync(a[i], As + (wm * 32 + i * 16) * LDA + k0, LDA);
#pragma unroll
            for (int j = 0; j < 4; j++)
                wmma::load_matrix_sync(b[j], Bs + (wn * 64 + j * 16) * LDA + k0, LDA);
#pragma unroll
            for (int i = 0; i < 2; i++)
#pragma unroll
                for (int j = 0; j < 4; j++)
                    wmma::mma_sync(c[i][j], a[i], b[j], c[i][j]);
        }
        __syncthreads();
    }

    float* stg = As + wid * (16 * LDS_STG);
    const int r = lane >> 1, cs = (lane & 1) * 8;
#pragma unroll
    for (int i = 0; i < 2; i++)
#pragma unroll
        for (int j = 0; j < 4; j++) {
            wmma::store_matrix_sync(stg, c[i][j], LDS_STG, wmma::mem_row_major);
            __syncwarp();
            const int gc = wn * 64 + j * 16 + cs;
            float* op = out + (size_t)(row0 + wm * 32 + i * 16 + r) * 512 + col0 + gc;
            float4 c0 = *(float4*)op;
            float4 c1 = *(float4*)(op + 4);
            float v0 = stg[r * LDS_STG + cs + 0];
            float v1v = stg[r * LDS_STG + cs + 1];
            float v2 = stg[r * LDS_STG + cs + 2];
            float v3 = stg[r * LDS_STG + cs + 3];
            float v4 = stg[r * LDS_STG + cs + 4];
            float v5 = stg[r * LDS_STG + cs + 5];
            float v6 = stg[r * LDS_STG + cs + 6];
            float v7 = stg[r * LDS_STG + cs + 7];
            c0.x += fmaxf(fmaf(v0,  s_alpha[gc + 0], s_beta[gc + 0]), 0.0f);
            c0.y += fmaxf(fmaf(v1v, s_alpha[gc + 1], s_beta[gc + 1]), 0.0f);
            c0.z += fmaxf(fmaf(v2,  s_alpha[gc + 2], s_beta[gc + 2]), 0.0f);
            c0.w += fmaxf(fmaf(v3,  s_alpha[gc + 3], s_beta[gc + 3]), 0.0f);
            c1.x += fmaxf(fmaf(v4,  s_alpha[gc + 4], s_beta[gc + 4]), 0.0f);
            c1.y += fmaxf(fmaf(v5,  s_alpha[gc + 5], s_beta[gc + 5]), 0.0f);
            c1.z += fmaxf(fmaf(v6,  s_alpha[gc + 6], s_beta[gc + 6]), 0.0f);
            c1.w += fmaxf(fmaf(v7,  s_alpha[gc + 7], s_beta[gc + 7]), 0.0f);
            *(float4*)op       = c0;
            *(float4*)(op + 4) = c1;
            __syncwarp();
        }
}

// ---------------- launch ----------------
extern "C" void kernel_launch(void* const* d_in, const int* in_sizes, int n_in,
                              void* d_out, int out_size) {
    const float* rgb     = (const float*)d_in[0];
    const float* depth   = (const float*)d_in[1];
    const float* mmwave  = (const float*)d_in[2];
    const float* lidar   = (const float*)d_in[3];
    const float* pts     = (const float*)d_in[4];
    const float* conv_w  = (const float*)d_in[5];
    const float* conv_b  = (const float*)d_in[6];
    const float* bn_g    = (const float*)d_in[7];
    const float* bn_b    = (const float*)d_in[8];
    const float* bn_m    = (const float*)d_in[9];
    const float* bn_v    = (const float*)d_in[10];
    const float* lwimg   = (const float*)d_in[11];
    const float* lbimg   = (const float*)d_in[12];
    const float* lwpc    = (const float*)d_in[13];
    const float* lbpc    = (const float*)d_in[14];
    const float* pw1     = (const float*)d_in[15];
    const float* pb1     = (const float*)d_in[16];
    const float* pg1     = (const float*)d_in[17];
    const float* pbb1    = (const float*)d_in[18];
    const float* pm1     = (const float*)d_in[19];
    const float* pv1     = (const float*)d_in[20];
    const float* pw2     = (const float*)d_in[21];
    const float* pb2     = (const float*)d_in[22];
    const float* pg2     = (const float*)d_in[23];
    const float* pbb2    = (const float*)d_in[24];
    const float* pm2     = (const float*)d_in[25];
    const float* pv2     = (const float*)d_in[26];
    float* out = (float*)d_out;

    // FPS (independent of GEMMs)
    fps_kernel<<<256, 256>>>(pts);

    // stage-1: all 4 modalities in one fused tf32 wmma launch (staging-time cvt)
    wmma_stage1_kernel<<<dim3(324, 4), 256>>>(rgb, depth, mmwave, lidar,
                                              conv_w, conv_b, bn_g, bn_b, bn_m, bn_v);

    // stage-2: proj written to d_out
    stage2_kernel<<<dim3(256, 4), 256>>>(lwimg, lbimg, lwpc, lbpc, out);

    // posenc: layer-1 fused into A-staging of the layer-2 tf32 GEMM, += into d_out
    wmma_posenc_kernel<<<dim3(256, 4), 256>>>(pw1, pb1, pg1, pbb1, pm1, pv1,
                                              pw2, pb2, pg2, pbb2, pm2, pv2, out);
}